// round 10
// baseline (speedup 1.0000x reference)
#include <cuda_runtime.h>
#include <cuda_fp16.h>
#include <cstdint>

// Problem constants
#define NN 50000
#define DD 128
#define EE 625000

typedef unsigned long long u64;

// Scratch (allocation-free rule: __device__ globals)
__device__ float  g_h[(size_t)NN * DD];        // layer-1 output (fp32)
__device__ __half g_feat16[(size_t)NN * DD];   // fp16 features (x16, then h16)
__device__ __half g_agg16[(size_t)NN * DD];    // fp16 aggregation buffer

// ---------------------------------------------------------------------------
// Zero kernel
// ---------------------------------------------------------------------------
__global__ void zero_kernel(float4* __restrict__ p, int n4) {
    int i = blockIdx.x * blockDim.x + threadIdx.x;
    if (i < n4) p[i] = make_float4(0.f, 0.f, 0.f, 0.f);
}

// ---------------------------------------------------------------------------
// fp32 -> fp16 convert (x -> x16)
// ---------------------------------------------------------------------------
__global__ void tohalf_kernel(const float4* __restrict__ src,
                              uint2* __restrict__ dst, int n4) {
    int i = blockIdx.x * blockDim.x + threadIdx.x;
    if (i < n4) {
        float4 v = src[i];
        __half2 a = __floats2half2_rn(v.x, v.y);
        __half2 b = __floats2half2_rn(v.z, v.w);
        dst[i] = make_uint2(*(unsigned*)&a, *(unsigned*)&b);
    }
}

// ---------------------------------------------------------------------------
// fp16 scatter-aggregate: one warp per 8 edges (proven R8 version).
// ---------------------------------------------------------------------------
#define EPW 8
__global__ void scatter16_kernel(const __half* __restrict__ feat,
                                 const int* __restrict__ ei,
                                 __half* __restrict__ agg) {
    int gw = (blockIdx.x * blockDim.x + threadIdx.x) >> 5;
    int lane = threadIdx.x & 31;
    int e0 = gw * EPW;
    if (e0 >= EE) return;
    int cnt = min(EPW, EE - e0);

    uint2 v[EPW];
    int d[EPW];
#pragma unroll
    for (int t = 0; t < EPW; t++) {
        if (t < cnt) {
            int e = e0 + t;
            int s = __ldg(&ei[e]);
            d[t] = __ldg(&ei[EE + e]);
            v[t] = ((const uint2*)(feat + (size_t)s * DD))[lane];
        }
    }
#pragma unroll
    for (int t = 0; t < EPW; t++) {
        if (t < cnt) {
            const __half* dp = agg + (size_t)d[t] * DD + lane * 4;
            asm volatile("red.global.add.noftz.v2.f16x2 [%0], {%1, %2};"
                         :: "l"(dp), "r"(v[t].x), "r"(v[t].y)
                         : "memory");
        }
    }
}

// ---------------------------------------------------------------------------
// Fused dual GEMM (FFMA2), 512 threads, unpack-free inner loop.
//   out[r][c] = act( A16[r]@Wrel + X[r]@Wroot + bias )[c]
// Tile: 128 rows x 128 cols. Thread: 4 rows x 4 col-pairs.
// A/X staged as DUPLICATED u64 pairs (value in both halves) so the inner
// loop is LDS.64 -> FFMA2 only. 4 stages of 32 k.
// Smem: 2*128*128*4 (W) + 2*128*32*8 (A2/X2) = 196608 B.
// ---------------------------------------------------------------------------
#define KC 32
#define GEMM_SMEM (2 * 128 * 128 * 4 + 2 * 128 * KC * 8)

__device__ __forceinline__ u64 dup2(float a) {
    u64 r;
    asm("mov.b64 %0, {%1, %1};" : "=l"(r) : "f"(a));
    return r;
}
__device__ __forceinline__ u64 ffma2(u64 a, u64 b, u64 c) {
    u64 d;
    asm("fma.rn.f32x2 %0, %1, %2, %3;" : "=l"(d) : "l"(a), "l"(b), "l"(c));
    return d;
}

__global__ __launch_bounds__(512, 1)
void gemm_kernel(const __half* __restrict__ A16,   // fp16 aggregate [N,128]
                 const float* __restrict__ X,      // fp32 root input [N,128]
                 const float* __restrict__ Wrel,
                 const float* __restrict__ Wroot,
                 const float* __restrict__ bias,
                 float* __restrict__ out,
                 __half* __restrict__ out16,       // optional fp16 copy
                 int relu) {
    extern __shared__ char smraw[];
    float* Wr = (float*)smraw;                    // 128*128
    float* Wo = Wr + 128 * 128;                   // 128*128
    u64* A2 = (u64*)(Wo + 128 * 128);             // [128][KC] duplicated
    u64* X2 = A2 + 128 * KC;                      // [128][KC] duplicated

    int tid = threadIdx.x;
    int row0 = blockIdx.x * 128;
    int tx = tid & 15;    // col-pairs: c = tx*2 + j*32
    int ty = tid >> 4;    // rows: r = ty*4 + i   (ty 0..31)

    // Stage both weight matrices (4096 float4 each, 8 iters/thread each)
    for (int i = tid; i < 128 * 128 / 4; i += 512) {
        ((float4*)Wr)[i] = ((const float4*)Wrel)[i];
        ((float4*)Wo)[i] = ((const float4*)Wroot)[i];
    }

    u64 acc[4][4];
#pragma unroll
    for (int i = 0; i < 4; i++)
#pragma unroll
        for (int j = 0; j < 4; j++) acc[i][j] = 0ull;

#pragma unroll 1
    for (int stage = 0; stage < 4; stage++) {
        int kb = stage * KC;
        __syncthreads();
        // Stage A (fp16 -> dup u64) and X (fp32 -> dup u64):
        // 128 rows x 8 chunks = 1024 work items over 512 threads (2 iters).
        for (int w = tid; w < 128 * 8; w += 512) {
            int r = w >> 3, c8 = w & 7;
            int grow = row0 + r;
            u64* a_dst = A2 + r * KC + c8 * 4;
            u64* x_dst = X2 + r * KC + c8 * 4;
            if (grow < NN) {
                uint2 u = *(const uint2*)(A16 + (size_t)grow * DD + kb + c8 * 4);
                float2 f0 = __half22float2(*(__half2*)&u.x);
                float2 f1 = __half22float2(*(__half2*)&u.y);
                a_dst[0] = dup2(f0.x); a_dst[1] = dup2(f0.y);
                a_dst[2] = dup2(f1.x); a_dst[3] = dup2(f1.y);
                float4 xv = *(const float4*)(X + (size_t)grow * DD + kb + c8 * 4);
                x_dst[0] = dup2(xv.x); x_dst[1] = dup2(xv.y);
                x_dst[2] = dup2(xv.z); x_dst[3] = dup2(xv.w);
            } else {
                a_dst[0] = a_dst[1] = a_dst[2] = a_dst[3] = 0ull;
                x_dst[0] = x_dst[1] = x_dst[2] = x_dst[3] = 0ull;
            }
        }
        __syncthreads();

#pragma unroll 4
        for (int kk = 0; kk < KC; kk++) {
            const float* wrk = Wr + (kb + kk) * 128;
            const float* wok = Wo + (kb + kk) * 128;
            u64 wr2[4], wo2[4];
#pragma unroll
            for (int j = 0; j < 4; j++) {
                wr2[j] = *(const u64*)(wrk + tx * 2 + j * 32);
                wo2[j] = *(const u64*)(wok + tx * 2 + j * 32);
            }
            u64 a2[4], x2[4];
#pragma unroll
            for (int i = 0; i < 4; i++) {
                a2[i] = A2[(ty * 4 + i) * KC + kk];
                x2[i] = X2[(ty * 4 + i) * KC + kk];
            }
#pragma unroll
            for (int i = 0; i < 4; i++)
#pragma unroll
                for (int j = 0; j < 4; j++) {
                    acc[i][j] = ffma2(a2[i], wr2[j], acc[i][j]);
                    acc[i][j] = ffma2(x2[i], wo2[j], acc[i][j]);
                }
        }
    }

    // Writeback
    float b0[4], b1[4];
#pragma unroll
    for (int j = 0; j < 4; j++) {
        int c = tx * 2 + j * 32;
        b0[j] = __ldg(&bias[c]);
        b1[j] = __ldg(&bias[c + 1]);
    }
#pragma unroll
    for (int i = 0; i < 4; i++) {
        int grow = row0 + ty * 4 + i;
        if (grow < NN) {
#pragma unroll
            for (int j = 0; j < 4; j++) {
                int c = tx * 2 + j * 32;
                float lo, hi;
                asm("mov.b64 {%0, %1}, %2;" : "=f"(lo), "=f"(hi) : "l"(acc[i][j]));
                lo += b0[j];
                hi += b1[j];
                if (relu) { lo = fmaxf(lo, 0.f); hi = fmaxf(hi, 0.f); }
                *(float2*)(out + (size_t)grow * DD + c) = make_float2(lo, hi);
                if (out16) {
                    __half2 hh = __floats2half2_rn(lo, hi);
                    *(__half2*)(out16 + (size_t)grow * DD + c) = hh;
                }
            }
        }
    }
}

// ---------------------------------------------------------------------------
// Launch
// ---------------------------------------------------------------------------
extern "C" void kernel_launch(void* const* d_in, const int* in_sizes, int n_in,
                              void* d_out, int out_size) {
    const float* x       = (const float*)d_in[0];
    const int*   ei      = (const int*)d_in[1];   // int32 (JAX x64 disabled)
    const float* W1_rel  = (const float*)d_in[2];
    const float* b1_rel  = (const float*)d_in[3];
    const float* W1_root = (const float*)d_in[4];
    const float* W2_rel  = (const float*)d_in[5];
    const float* b2_rel  = (const float*)d_in[6];
    const float* W2_root = (const float*)d_in[7];
    float*       out     = (float*)d_out;

    float  *h;
    __half *feat16, *agg16;
    cudaGetSymbolAddress((void**)&h, g_h);
    cudaGetSymbolAddress((void**)&feat16, g_feat16);
    cudaGetSymbolAddress((void**)&agg16, g_agg16);

    cudaFuncSetAttribute(gemm_kernel,
                         cudaFuncAttributeMaxDynamicSharedMemorySize,
                         (int)GEMM_SMEM);

    const int n4 = NN * DD / 4;                  // float4 count (fp32)
    const int n4h = NN * DD * 2 / 16;            // float4 count (fp16 buffer)
    const int cgrid = (n4 + 255) / 256;
    const int zgrid = (n4h + 255) / 256;
    const int nwarp = (EE + EPW - 1) / EPW;
    const int sgrid = (nwarp * 32 + 255) / 256;
    const int ggrid = (NN + 127) / 128;

    // x -> fp16
    tohalf_kernel<<<cgrid, 256>>>((const float4*)x, (uint2*)feat16, n4);

    // Layer 1  (gemm also emits h16 into feat16 for the next scatter)
    zero_kernel<<<zgrid, 256>>>((float4*)agg16, n4h);
    scatter16_kernel<<<sgrid, 256>>>(feat16, ei, agg16);
    gemm_kernel<<<ggrid, 512, GEMM_SMEM>>>(agg16, x, W1_rel, W1_root, b1_rel,
                                           h, feat16, 1);

    // Layer 2
    zero_kernel<<<zgrid, 256>>>((float4*)agg16, n4h);
    scatter16_kernel<<<sgrid, 256>>>(feat16, ei, agg16);
    gemm_kernel<<<ggrid, 512, GEMM_SMEM>>>(agg16, h, W2_rel, W2_root, b2_rel,
                                           out, (__half*)nullptr, 0);
}

// round 11
// speedup vs baseline: 1.3737x; 1.3737x over previous
#include <cuda_runtime.h>
#include <cuda_fp16.h>
#include <cstdint>

// Problem constants
#define NN 50000
#define DD 128
#define EE 625000
#define PST 136          // padded row stride in halves (272 B) for ldmatrix tiles

// Scratch (allocation-free rule: __device__ globals)
__device__ __half g_agg16[(size_t)NN * DD];
__device__ __half g_xh[(size_t)NN * DD];
__device__ __half g_xl[(size_t)NN * DD];
__device__ __half g_hh[(size_t)NN * DD];
__device__ __half g_hl[(size_t)NN * DD];
// Transposed fp16 hi/lo weights, padded [128 n][PST k]:
// index m: 0=W1_rel 1=W1_root 2=W2_rel 3=W2_root
__device__ __half g_wth[4 * 128 * PST];
__device__ __half g_wtl[4 * 128 * PST];

// ---------------------------------------------------------------------------
// Zero kernel
// ---------------------------------------------------------------------------
__global__ void zero_kernel(float4* __restrict__ p, int n4) {
    int i = blockIdx.x * blockDim.x + threadIdx.x;
    if (i < n4) p[i] = make_float4(0.f, 0.f, 0.f, 0.f);
}

// ---------------------------------------------------------------------------
// x -> (xh, xl) fp16 split
// ---------------------------------------------------------------------------
__global__ void xprep_kernel(const float2* __restrict__ x,
                             unsigned* __restrict__ xh,
                             unsigned* __restrict__ xl, int n2) {
    int i = blockIdx.x * blockDim.x + threadIdx.x;
    if (i < n2) {
        float2 v = x[i];
        __half2 h = __floats2half2_rn(v.x, v.y);
        float2 hf = __half22float2(h);
        __half2 l = __floats2half2_rn(v.x - hf.x, v.y - hf.y);
        xh[i] = *(unsigned*)&h;
        xl[i] = *(unsigned*)&l;
    }
}

// ---------------------------------------------------------------------------
// Weight prep: W[k][n] fp32 -> W^T hi/lo fp16 padded [n][PST]
// ---------------------------------------------------------------------------
__global__ void wprep_kernel(const float* __restrict__ w0,
                             const float* __restrict__ w1,
                             const float* __restrict__ w2,
                             const float* __restrict__ w3,
                             __half* __restrict__ wth,
                             __half* __restrict__ wtl) {
    int g = blockIdx.x * blockDim.x + threadIdx.x;
    if (g >= 4 * 128 * 128) return;
    int m = g >> 14, e = g & 16383;
    int n = e >> 7, k = e & 127;
    const float* W = (m == 0) ? w0 : (m == 1) ? w1 : (m == 2) ? w2 : w3;
    float w = W[k * 128 + n];
    __half hi = __float2half_rn(w);
    __half lo = __float2half_rn(w - __half2float(hi));
    wth[m * 128 * PST + n * PST + k] = hi;
    wtl[m * 128 * PST + n * PST + k] = lo;
}

// ---------------------------------------------------------------------------
// fp16 scatter-aggregate: one warp per 8 edges (proven R8 version).
// ---------------------------------------------------------------------------
#define EPW 8
__global__ void scatter16_kernel(const __half* __restrict__ feat,
                                 const int* __restrict__ ei,
                                 __half* __restrict__ agg) {
    int gw = (blockIdx.x * blockDim.x + threadIdx.x) >> 5;
    int lane = threadIdx.x & 31;
    int e0 = gw * EPW;
    if (e0 >= EE) return;
    int cnt = min(EPW, EE - e0);

    uint2 v[EPW];
    int d[EPW];
#pragma unroll
    for (int t = 0; t < EPW; t++) {
        if (t < cnt) {
            int e = e0 + t;
            int s = __ldg(&ei[e]);
            d[t] = __ldg(&ei[EE + e]);
            v[t] = ((const uint2*)(feat + (size_t)s * DD))[lane];
        }
    }
#pragma unroll
    for (int t = 0; t < EPW; t++) {
        if (t < cnt) {
            const __half* dp = agg + (size_t)d[t] * DD + lane * 4;
            asm volatile("red.global.add.noftz.v2.f16x2 [%0], {%1, %2};"
                         :: "l"(dp), "r"(v[t].x), "r"(v[t].y)
                         : "memory");
        }
    }
}

// ---------------------------------------------------------------------------
// MMA GEMM: out = act( agg@Wrel + X@Wroot + bias ), via m16n8k16 fp16 HMMA.
// 5 passes accumulate into fp32 D fragments:
//   (agg, Wrel_hi) (agg, Wrel_lo) (Xh, Wroot_hi) (Xl, Wroot_hi) (Xh, Wroot_lo)
// Tile 128x128, 512 threads / 16 warps; warp tile 16(m) x 64(n).
// Smem: 3 A-tiles [128][PST]h + 1 W slot [128][PST]h = 139264 B.
// ---------------------------------------------------------------------------
#define GSM_A  0
#define GSM_XH 34816
#define GSM_XL 69632
#define GSM_W  104448
#define GSMEM  139264

__device__ __forceinline__ uint32_t smem_u32(const void* p) {
    uint32_t a;
    asm("{ .reg .u64 t; cvta.to.shared.u64 t, %1; cvt.u32.u64 %0, t; }"
        : "=r"(a) : "l"(p));
    return a;
}

__global__ __launch_bounds__(512, 1)
void gemm_mma_kernel(const __half* __restrict__ A16,  // aggregated fp16 [N,128]
                     const __half* __restrict__ Xh,   // root hi [N,128]
                     const __half* __restrict__ Xl,   // root lo [N,128]
                     const __half* __restrict__ wth_rel,
                     const __half* __restrict__ wtl_rel,
                     const __half* __restrict__ wth_root,
                     const __half* __restrict__ wtl_root,
                     const float* __restrict__ bias,
                     float* __restrict__ out32,       // fp32 out (or null)
                     __half* __restrict__ outh,       // fp16 hi out (or null)
                     __half* __restrict__ outl,       // fp16 lo out (or null)
                     int relu) {
    extern __shared__ char sm[];
    uint32_t sbase = smem_u32(sm);
    int tid = threadIdx.x, wid = tid >> 5, lane = tid & 31;
    int row0 = blockIdx.x * 128;

    // Stage 3 A-tiles: global [N][128]h -> smem [128][PST]h (row pad 272 B)
    for (int w = tid; w < 128 * 16; w += 512) {
        int r = w >> 4, c = w & 15;   // c: uint4 chunk (8 halves)
        int grow = row0 + r;
        uint4 va, vh, vl;
        if (grow < NN) {
            va = ((const uint4*)(A16 + (size_t)grow * DD))[c];
            vh = ((const uint4*)(Xh + (size_t)grow * DD))[c];
            vl = ((const uint4*)(Xl + (size_t)grow * DD))[c];
        } else {
            va = make_uint4(0, 0, 0, 0);
            vh = va; vl = va;
        }
        *(uint4*)(sm + GSM_A  + r * 272 + c * 16) = va;
        *(uint4*)(sm + GSM_XH + r * 272 + c * 16) = vh;
        *(uint4*)(sm + GSM_XL + r * 272 + c * 16) = vl;
    }

    int rw = wid & 7;       // row-block: rows rw*16..+15
    int cw = wid >> 3;      // col-block: cols cw*64..+63

    float d[8][4];
#pragma unroll
    for (int i = 0; i < 8; i++)
#pragma unroll
        for (int j = 0; j < 4; j++) d[i][j] = 0.f;

    // ldmatrix per-lane address components
    // A x4: lanes 0-7: mat0 rows 0-7 @k0 | 8-15: rows 8-15 @k0
    //       | 16-23: rows 0-7 @k8 | 24-31: rows 8-15 @k8
    int a_row  = rw * 16 + ((lane >> 3) & 1) * 8 + (lane & 7);
    int a_koff = (lane >> 4) * 8;
    uint32_t a_off = (uint32_t)(a_row * 272 + a_koff * 2);
    // B x4 (covers 2 n-frags): mat = lane>>3:
    //   n = cw*64 + bq*16 + (mat>>1)*8 + lane&7 ; k-half = (mat&1)*8
    int b_mat = lane >> 3;
    int b_line = cw * 64 + ((b_mat >> 1) & 1) * 8 + (lane & 7);
    int b_koff = (b_mat & 1) * 8;
    uint32_t b_off = sbase + GSM_W + (uint32_t)(b_line * 272 + b_koff * 2);

    const uint32_t aoff[5]  = {GSM_A, GSM_A, GSM_XH, GSM_XL, GSM_XH};
    const __half* wsrc[5] = {wth_rel, wtl_rel, wth_root, wth_root, wtl_root};
    const int stagew[5] = {1, 1, 1, 0, 1};  // pass 3 reuses pass 2's W

#pragma unroll 1
    for (int p = 0; p < 5; p++) {
        __syncthreads();   // A-tiles ready (p0) / prior mma reads of W done
        if (stagew[p]) {
            const uint4* src = (const uint4*)wsrc[p];
            for (int i = tid; i < 2176; i += 512)
                ((uint4*)(sm + GSM_W))[i] = src[i];
        }
        __syncthreads();

        uint32_t abase = sbase + aoff[p] + a_off;
#pragma unroll
        for (int ks = 0; ks < 8; ks++) {
            uint32_t a0, a1, a2, a3;
            asm volatile(
                "ldmatrix.sync.aligned.m8n8.x4.shared.b16 {%0,%1,%2,%3}, [%4];"
                : "=r"(a0), "=r"(a1), "=r"(a2), "=r"(a3)
                : "r"(abase + ks * 32));
            uint32_t b[4][4];
#pragma unroll
            for (int bq = 0; bq < 4; bq++) {
                asm volatile(
                    "ldmatrix.sync.aligned.m8n8.x4.shared.b16 {%0,%1,%2,%3}, [%4];"
                    : "=r"(b[bq][0]), "=r"(b[bq][1]), "=r"(b[bq][2]), "=r"(b[bq][3])
                    : "r"(b_off + bq * (16 * 272) + ks * 32));
            }
#pragma unroll
            for (int nf = 0; nf < 8; nf++) {
                uint32_t b0 = b[nf >> 1][(nf & 1) * 2];
                uint32_t b1 = b[nf >> 1][(nf & 1) * 2 + 1];
                asm volatile(
                    "mma.sync.aligned.m16n8k16.row.col.f32.f16.f16.f32 "
                    "{%0,%1,%2,%3}, {%4,%5,%6,%7}, {%8,%9}, {%0,%1,%2,%3};"
                    : "+f"(d[nf][0]), "+f"(d[nf][1]), "+f"(d[nf][2]), "+f"(d[nf][3])
                    : "r"(a0), "r"(a1), "r"(a2), "r"(a3), "r"(b0), "r"(b1));
            }
        }
    }

    // Epilogue straight from fragments.
    // d0,d1: (row = rw*16 + lane/4, col = cw*64 + nf*8 + 2(lane%4) +0/1)
    // d2,d3: row + 8
    int er0 = row0 + rw * 16 + (lane >> 2);
#pragma unroll
    for (int nf = 0; nf < 8; nf++) {
        int c = cw * 64 + nf * 8 + 2 * (lane & 3);
        float bz0 = __ldg(&bias[c]);
        float bz1 = __ldg(&bias[c + 1]);
#pragma unroll
        for (int half = 0; half < 2; half++) {
            int grow = er0 + half * 8;
            if (grow < NN) {
                float v0 = d[nf][half * 2 + 0] + bz0;
                float v1 = d[nf][half * 2 + 1] + bz1;
                if (relu) { v0 = fmaxf(v0, 0.f); v1 = fmaxf(v1, 0.f); }
                if (out32)
                    *(float2*)(out32 + (size_t)grow * DD + c) = make_float2(v0, v1);
                if (outh) {
                    __half2 hh = __floats2half2_rn(v0, v1);
                    *(__half2*)(outh + (size_t)grow * DD + c) = hh;
                    float2 hf = __half22float2(hh);
                    __half2 ll = __floats2half2_rn(v0 - hf.x, v1 - hf.y);
                    *(__half2*)(outl + (size_t)grow * DD + c) = ll;
                }
            }
        }
    }
}

// ---------------------------------------------------------------------------
// Launch
// ---------------------------------------------------------------------------
extern "C" void kernel_launch(void* const* d_in, const int* in_sizes, int n_in,
                              void* d_out, int out_size) {
    const float* x       = (const float*)d_in[0];
    const int*   ei      = (const int*)d_in[1];   // int32 (JAX x64 disabled)
    const float* W1_rel  = (const float*)d_in[2];
    const float* b1_rel  = (const float*)d_in[3];
    const float* W1_root = (const float*)d_in[4];
    const float* W2_rel  = (const float*)d_in[5];
    const float* b2_rel  = (const float*)d_in[6];
    const float* W2_root = (const float*)d_in[7];
    float*       out     = (float*)d_out;

    __half *agg16, *xh, *xl, *hh, *hl, *wth, *wtl;
    cudaGetSymbolAddress((void**)&agg16, g_agg16);
    cudaGetSymbolAddress((void**)&xh, g_xh);
    cudaGetSymbolAddress((void**)&xl, g_xl);
    cudaGetSymbolAddress((void**)&hh, g_hh);
    cudaGetSymbolAddress((void**)&hl, g_hl);
    cudaGetSymbolAddress((void**)&wth, g_wth);
    cudaGetSymbolAddress((void**)&wtl, g_wtl);

    cudaFuncSetAttribute(gemm_mma_kernel,
                         cudaFuncAttributeMaxDynamicSharedMemorySize,
                         (int)GSMEM);

    const int n2 = NN * DD / 2;
    const int n4h = NN * DD * 2 / 16;            // float4 count of fp16 buffer
    const int zgrid = (n4h + 255) / 256;
    const int nwarp = (EE + EPW - 1) / EPW;
    const int sgrid = (nwarp * 32 + 255) / 256;
    const int ggrid = (NN + 127) / 128;          // 391

    // Prep (once per launch)
    xprep_kernel<<<(n2 + 255) / 256, 256>>>((const float2*)x,
                                            (unsigned*)xh, (unsigned*)xl, n2);
    wprep_kernel<<<(4 * 16384 + 255) / 256, 256>>>(W1_rel, W1_root,
                                                   W2_rel, W2_root, wth, wtl);

    const int WM = 128 * PST;  // halves per weight tile

    // Layer 1: A=agg(xh), X=xh/xl; emits hh/hl
    zero_kernel<<<zgrid, 256>>>((float4*)agg16, n4h);
    scatter16_kernel<<<sgrid, 256>>>(xh, ei, agg16);
    gemm_mma_kernel<<<ggrid, 512, GSMEM>>>(agg16, xh, xl,
                                           wth + 0 * WM, wtl + 0 * WM,
                                           wth + 1 * WM, wtl + 1 * WM,
                                           b1_rel, nullptr, hh, hl, 1);

    // Layer 2: A=agg(hh), X=hh/hl; emits fp32 out
    zero_kernel<<<zgrid, 256>>>((float4*)agg16, n4h);
    scatter16_kernel<<<sgrid, 256>>>(hh, ei, agg16);
    gemm_mma_kernel<<<ggrid, 512, GSMEM>>>(agg16, hh, hl,
                                           wth + 2 * WM, wtl + 2 * WM,
                                           wth + 3 * WM, wtl + 3 * WM,
                                           b2_rel, out, nullptr, nullptr, 0);
}

// round 12
// speedup vs baseline: 1.5073x; 1.0973x over previous
#include <cuda_runtime.h>
#include <cuda_fp16.h>
#include <cstdint>

// Problem constants
#define NN 50000
#define DD 128
#define EE 625000
#define PST 136          // padded row stride in halves (272 B) for ldmatrix tiles

// Scratch (allocation-free rule: __device__ globals)
__device__ __half g_agg16[(size_t)NN * DD];
__device__ __half g_xh[(size_t)NN * DD];
__device__ __half g_xl[(size_t)NN * DD];
__device__ __half g_hh[(size_t)NN * DD];
__device__ __half g_hl[(size_t)NN * DD];
// Transposed fp16 hi/lo weights, padded [128 n][PST k]:
// 0=W1_rel 1=W1_root 2=W2_rel 3=W2_root
__device__ __half g_wth[4 * 128 * PST];
__device__ __half g_wtl[4 * 128 * PST];

// ---------------------------------------------------------------------------
// Zero kernel
// ---------------------------------------------------------------------------
__global__ void zero_kernel(float4* __restrict__ p, int n4) {
    int i = blockIdx.x * blockDim.x + threadIdx.x;
    if (i < n4) p[i] = make_float4(0.f, 0.f, 0.f, 0.f);
}

// ---------------------------------------------------------------------------
// x -> (xh, xl) fp16 split
// ---------------------------------------------------------------------------
__global__ void xprep_kernel(const float2* __restrict__ x,
                             unsigned* __restrict__ xh,
                             unsigned* __restrict__ xl, int n2) {
    int i = blockIdx.x * blockDim.x + threadIdx.x;
    if (i < n2) {
        float2 v = x[i];
        __half2 h = __floats2half2_rn(v.x, v.y);
        float2 hf = __half22float2(h);
        __half2 l = __floats2half2_rn(v.x - hf.x, v.y - hf.y);
        xh[i] = *(unsigned*)&h;
        xl[i] = *(unsigned*)&l;
    }
}

// ---------------------------------------------------------------------------
// Weight prep: W[k][n] fp32 -> W^T hi/lo fp16 padded [n][PST]
// ---------------------------------------------------------------------------
__global__ void wprep_kernel(const float* __restrict__ w0,
                             const float* __restrict__ w1,
                             const float* __restrict__ w2,
                             const float* __restrict__ w3,
                             __half* __restrict__ wth,
                             __half* __restrict__ wtl) {
    int g = blockIdx.x * blockDim.x + threadIdx.x;
    if (g >= 4 * 128 * 128) return;
    int m = g >> 14, e = g & 16383;
    int n = e >> 7, k = e & 127;
    const float* W = (m == 0) ? w0 : (m == 1) ? w1 : (m == 2) ? w2 : w3;
    float w = W[k * 128 + n];
    __half hi = __float2half_rn(w);
    __half lo = __float2half_rn(w - __half2float(hi));
    wth[m * 128 * PST + n * PST + k] = hi;
    wtl[m * 128 * PST + n * PST + k] = lo;
}

// ---------------------------------------------------------------------------
// fp16 scatter-aggregate: half-warp per edge, 128-bit REDs.
//   Lanes 0-15 handle edge 2t, lanes 16-31 edge 2t+1; each lane 16 bytes.
//   red.global.add.noftz.v4.f16x2 quarters the RED op count vs v2.
// ---------------------------------------------------------------------------
#define EPW 8
__global__ void scatter16_kernel(const __half* __restrict__ feat,
                                 const int* __restrict__ ei,
                                 __half* __restrict__ agg) {
    int gw = (blockIdx.x * blockDim.x + threadIdx.x) >> 5;
    int lane = threadIdx.x & 31;
    int half = lane >> 4;          // 0/1: which edge of the pair
    int hl = lane & 15;            // 16 lanes x 16B = 256B row
    int e0 = gw * EPW;
    if (e0 >= EE) return;

    uint4 v[EPW / 2];
    int d[EPW / 2];
#pragma unroll
    for (int t = 0; t < EPW / 2; t++) {
        int e = e0 + 2 * t + half;
        if (e < EE) {
            int s = __ldg(&ei[e]);
            d[t] = __ldg(&ei[EE + e]);
            v[t] = ((const uint4*)(feat + (size_t)s * DD))[hl];
        }
    }
#pragma unroll
    for (int t = 0; t < EPW / 2; t++) {
        int e = e0 + 2 * t + half;
        if (e < EE) {
            const __half* dp = agg + (size_t)d[t] * DD + hl * 8;
            asm volatile("red.global.add.noftz.v4.f16x2 [%0], {%1, %2, %3, %4};"
                         :: "l"(dp), "r"(v[t].x), "r"(v[t].y),
                            "r"(v[t].z), "r"(v[t].w)
                         : "memory");
        }
    }
}

// ---------------------------------------------------------------------------
// MMA GEMM: out = act( agg@Wrel + X@Wroot + bias ), m16n8k16 fp16 HMMA.
// 5 passes accumulate into fp32 D fragments:
//   (agg, Wrel_hi) (agg, Wrel_lo) (Xh, Wroot_hi) (Xl, Wroot_hi) (Xh, Wroot_lo)
// W tiles double-buffered: pass p+1's W staged while pass p's MMAs run.
// Optionally zeroes the consumed A16 rows in the epilogue (for next layer).
// Smem: 3 A-tiles + 2 W slots, each 34816 B = 174080 B.
// ---------------------------------------------------------------------------
#define GSM_A   0
#define GSM_XH  34816
#define GSM_XL  69632
#define GSM_W0  104448
#define GSM_W1  139264
#define GSMEM   174080

__device__ __forceinline__ uint32_t smem_u32(const void* p) {
    uint32_t a;
    asm("{ .reg .u64 t; cvta.to.shared.u64 t, %1; cvt.u32.u64 %0, t; }"
        : "=r"(a) : "l"(p));
    return a;
}

__global__ __launch_bounds__(512, 1)
void gemm_mma_kernel(const __half* __restrict__ A16,  // aggregated fp16 [N,128]
                     __half* __restrict__ aggz,       // same buffer, to zero (or null)
                     const __half* __restrict__ Xh,
                     const __half* __restrict__ Xl,
                     const __half* __restrict__ wth_rel,
                     const __half* __restrict__ wtl_rel,
                     const __half* __restrict__ wth_root,
                     const __half* __restrict__ wtl_root,
                     const float* __restrict__ bias,
                     float* __restrict__ out32,       // fp32 out (or null)
                     __half* __restrict__ outh,       // fp16 hi out (or null)
                     __half* __restrict__ outl,       // fp16 lo out (or null)
                     int relu) {
    extern __shared__ char sm[];
    uint32_t sbase = smem_u32(sm);
    int tid = threadIdx.x, wid = tid >> 5, lane = tid & 31;
    int row0 = blockIdx.x * 128;

    // Stage 3 A-tiles: global [N][128]h -> smem [128][PST]h (row pad 272 B)
    for (int w = tid; w < 128 * 16; w += 512) {
        int r = w >> 4, c = w & 15;
        int grow = row0 + r;
        uint4 va, vh, vl;
        if (grow < NN) {
            va = ((const uint4*)(A16 + (size_t)grow * DD))[c];
            vh = ((const uint4*)(Xh + (size_t)grow * DD))[c];
            vl = ((const uint4*)(Xl + (size_t)grow * DD))[c];
        } else {
            va = make_uint4(0, 0, 0, 0);
            vh = va; vl = va;
        }
        *(uint4*)(sm + GSM_A  + r * 272 + c * 16) = va;
        *(uint4*)(sm + GSM_XH + r * 272 + c * 16) = vh;
        *(uint4*)(sm + GSM_XL + r * 272 + c * 16) = vl;
    }
    // Pre-stage pass-0 W (Wrel_hi) into slot 0
    for (int i = tid; i < 2176; i += 512)
        ((uint4*)(sm + GSM_W0))[i] = ((const uint4*)wth_rel)[i];
    __syncthreads();

    int rw = wid & 7;       // row-block
    int cw = wid >> 3;      // col-block

    float d[8][4];
#pragma unroll
    for (int i = 0; i < 8; i++)
#pragma unroll
        for (int j = 0; j < 4; j++) d[i][j] = 0.f;

    int a_row  = rw * 16 + ((lane >> 3) & 1) * 8 + (lane & 7);
    int a_koff = (lane >> 4) * 8;
    uint32_t a_off = (uint32_t)(a_row * 272 + a_koff * 2);
    int b_mat = lane >> 3;
    int b_line = cw * 64 + ((b_mat >> 1) & 1) * 8 + (lane & 7);
    int b_koff = (b_mat & 1) * 8;
    uint32_t b_rel = (uint32_t)(b_line * 272 + b_koff * 2);

    const uint32_t aoff[5] = {GSM_A, GSM_A, GSM_XH, GSM_XL, GSM_XH};
    const int wslot[5] = {0, 1, 0, 0, 1};          // which slot pass p reads
    const __half* wnext[5] = {wtl_rel, wth_root, nullptr, wtl_root, nullptr};
    // wnext[p] = W to stage during pass p (for pass p+1); null = no copy.

#pragma unroll 1
    for (int p = 0; p < 5; p++) {
        // Stage next pass's W into the other slot (overlaps with MMAs below)
        if (wnext[p]) {
            uint32_t dstoff = (wslot[p + 1] == 0) ? GSM_W0 : GSM_W1;
            const uint4* src = (const uint4*)wnext[p];
            for (int i = tid; i < 2176; i += 512)
                ((uint4*)(sm + dstoff))[i] = src[i];
        }

        uint32_t abase = sbase + aoff[p] + a_off;
        uint32_t b_off = sbase + ((wslot[p] == 0) ? GSM_W0 : GSM_W1) + b_rel;
#pragma unroll
        for (int ks = 0; ks < 8; ks++) {
            uint32_t a0, a1, a2, a3;
            asm volatile(
                "ldmatrix.sync.aligned.m8n8.x4.shared.b16 {%0,%1,%2,%3}, [%4];"
                : "=r"(a0), "=r"(a1), "=r"(a2), "=r"(a3)
                : "r"(abase + ks * 32));
            uint32_t b[4][4];
#pragma unroll
            for (int bq = 0; bq < 4; bq++) {
                asm volatile(
                    "ldmatrix.sync.aligned.m8n8.x4.shared.b16 {%0,%1,%2,%3}, [%4];"
                    : "=r"(b[bq][0]), "=r"(b[bq][1]), "=r"(b[bq][2]), "=r"(b[bq][3])
                    : "r"(b_off + bq * (16 * 272) + ks * 32));
            }
#pragma unroll
            for (int nf = 0; nf < 8; nf++) {
                uint32_t b0 = b[nf >> 1][(nf & 1) * 2];
                uint32_t b1 = b[nf >> 1][(nf & 1) * 2 + 1];
                asm volatile(
                    "mma.sync.aligned.m16n8k16.row.col.f32.f16.f16.f32 "
                    "{%0,%1,%2,%3}, {%4,%5,%6,%7}, {%8,%9}, {%0,%1,%2,%3};"
                    : "+f"(d[nf][0]), "+f"(d[nf][1]), "+f"(d[nf][2]), "+f"(d[nf][3])
                    : "r"(a0), "r"(a1), "r"(a2), "r"(a3), "r"(b0), "r"(b1));
            }
        }
        __syncthreads();   // W(p+1) staged AND everyone done reading W(p)
    }

    // Zero the consumed aggregate rows for the next layer's scatter
    if (aggz) {
        uint4 z = make_uint4(0, 0, 0, 0);
        for (int w = tid; w < 128 * 16; w += 512) {
            int r = w >> 4, c = w & 15;
            int grow = row0 + r;
            if (grow < NN) ((uint4*)(aggz + (size_t)grow * DD))[c] = z;
        }
    }

    // Epilogue straight from fragments
    int er0 = row0 + rw * 16 + (lane >> 2);
#pragma unroll
    for (int nf = 0; nf < 8; nf++) {
        int c = cw * 64 + nf * 8 + 2 * (lane & 3);
        float bz0 = __ldg(&bias[c]);
        float bz1 = __ldg(&bias[c + 1]);
#pragma unroll
        for (int half = 0; half < 2; half++) {
            int grow = er0 + half * 8;
            if (grow < NN) {
                float v0 = d[nf][half * 2 + 0] + bz0;
                float v1 = d[nf][half * 2 + 1] + bz1;
                if (relu) { v0 = fmaxf(v0, 0.f); v1 = fmaxf(v1, 0.f); }
                if (out32)
                    *(float2*)(out32 + (size_t)grow * DD + c) = make_float2(v0, v1);
                if (outh) {
                    __half2 hh = __floats2half2_rn(v0, v1);
                    *(__half2*)(outh + (size_t)grow * DD + c) = hh;
                    float2 hf = __half22float2(hh);
                    __half2 ll = __floats2half2_rn(v0 - hf.x, v1 - hf.y);
                    *(__half2*)(outl + (size_t)grow * DD + c) = ll;
                }
            }
        }
    }
}

// ---------------------------------------------------------------------------
// Launch
// ---------------------------------------------------------------------------
extern "C" void kernel_launch(void* const* d_in, const int* in_sizes, int n_in,
                              void* d_out, int out_size) {
    const float* x       = (const float*)d_in[0];
    const int*   ei      = (const int*)d_in[1];   // int32 (JAX x64 disabled)
    const float* W1_rel  = (const float*)d_in[2];
    const float* b1_rel  = (const float*)d_in[3];
    const float* W1_root = (const float*)d_in[4];
    const float* W2_rel  = (const float*)d_in[5];
    const float* b2_rel  = (const float*)d_in[6];
    const float* W2_root = (const float*)d_in[7];
    float*       out     = (float*)d_out;

    __half *agg16, *xh, *xl, *hh, *hl, *wth, *wtl;
    cudaGetSymbolAddress((void**)&agg16, g_agg16);
    cudaGetSymbolAddress((void**)&xh, g_xh);
    cudaGetSymbolAddress((void**)&xl, g_xl);
    cudaGetSymbolAddress((void**)&hh, g_hh);
    cudaGetSymbolAddress((void**)&hl, g_hl);
    cudaGetSymbolAddress((void**)&wth, g_wth);
    cudaGetSymbolAddress((void**)&wtl, g_wtl);

    cudaFuncSetAttribute(gemm_mma_kernel,
                         cudaFuncAttributeMaxDynamicSharedMemorySize,
                         (int)GSMEM);

    const int n2 = NN * DD / 2;
    const int n4h = NN * DD * 2 / 16;
    const int zgrid = (n4h + 255) / 256;
    const int nwarp = (EE + EPW - 1) / EPW;
    const int sgrid = (nwarp * 32 + 255) / 256;
    const int ggrid = (NN + 127) / 128;          // 391

    // Prep (once per launch)
    xprep_kernel<<<(n2 + 255) / 256, 256>>>((const float2*)x,
                                            (unsigned*)xh, (unsigned*)xl, n2);
    wprep_kernel<<<(4 * 16384 + 255) / 256, 256>>>(W1_rel, W1_root,
                                                   W2_rel, W2_root, wth, wtl);

    const int WM = 128 * PST;

    // Layer 1: A=agg(xh), X=xh/xl; emits hh/hl; zeroes agg16 for layer 2
    zero_kernel<<<zgrid, 256>>>((float4*)agg16, n4h);
    scatter16_kernel<<<sgrid, 256>>>(xh, ei, agg16);
    gemm_mma_kernel<<<ggrid, 512, GSMEM>>>(agg16, agg16, xh, xl,
                                           wth + 0 * WM, wtl + 0 * WM,
                                           wth + 1 * WM, wtl + 1 * WM,
                                           b1_rel, nullptr, hh, hl, 1);

    // Layer 2: A=agg(hh), X=hh/hl; emits fp32 out
    scatter16_kernel<<<sgrid, 256>>>(hh, ei, agg16);
    gemm_mma_kernel<<<ggrid, 512, GSMEM>>>(agg16, nullptr, hh, hl,
                                           wth + 2 * WM, wtl + 2 * WM,
                                           wth + 3 * WM, wtl + 3 * WM,
                                           b2_rel, out, nullptr, nullptr, 0);
}

// round 13
// speedup vs baseline: 1.9330x; 1.2824x over previous
#include <cuda_runtime.h>
#include <cuda_fp16.h>
#include <cstdint>

// Problem constants
#define NN 50000
#define DD 128
#define EE 625000
#define PST 136          // padded row stride in halves (272 B) for ldmatrix

// Scratch (allocation-free rule: __device__ globals)
__device__ __half g_agg16[(size_t)NN * DD];
__device__ __half g_xh[(size_t)NN * DD];
__device__ __half g_hh[(size_t)NN * DD];
// Transposed fp16 hi/lo weights, padded [128 n][PST k]:
// 0=W1_rel 1=W1_root 2=W2_rel 3=W2_root
__device__ __half g_wth[4 * 128 * PST];
__device__ __half g_wtl[4 * 128 * PST];

// ---------------------------------------------------------------------------
// Zero kernel
// ---------------------------------------------------------------------------
__global__ void zero_kernel(float4* __restrict__ p, int n4) {
    int i = blockIdx.x * blockDim.x + threadIdx.x;
    if (i < n4) p[i] = make_float4(0.f, 0.f, 0.f, 0.f);
}

// ---------------------------------------------------------------------------
// fp32 -> fp16 convert (x -> xh)
// ---------------------------------------------------------------------------
__global__ void tohalf_kernel(const float4* __restrict__ src,
                              uint2* __restrict__ dst, int n4) {
    int i = blockIdx.x * blockDim.x + threadIdx.x;
    if (i < n4) {
        float4 v = src[i];
        __half2 a = __floats2half2_rn(v.x, v.y);
        __half2 b = __floats2half2_rn(v.z, v.w);
        dst[i] = make_uint2(*(unsigned*)&a, *(unsigned*)&b);
    }
}

// ---------------------------------------------------------------------------
// Weight prep: W[k][n] fp32 -> W^T hi/lo fp16 padded [n][PST]
// ---------------------------------------------------------------------------
__global__ void wprep_kernel(const float* __restrict__ w0,
                             const float* __restrict__ w1,
                             const float* __restrict__ w2,
                             const float* __restrict__ w3,
                             __half* __restrict__ wth,
                             __half* __restrict__ wtl) {
    int g = blockIdx.x * blockDim.x + threadIdx.x;
    if (g >= 4 * 128 * 128) return;
    int m = g >> 14, e = g & 16383;
    int n = e >> 7, k = e & 127;
    const float* W = (m == 0) ? w0 : (m == 1) ? w1 : (m == 2) ? w2 : w3;
    float w = W[k * 128 + n];
    __half hi = __float2half_rn(w);
    __half lo = __float2half_rn(w - __half2float(hi));
    wth[m * 128 * PST + n * PST + k] = hi;
    wtl[m * 128 * PST + n * PST + k] = lo;
}

// ---------------------------------------------------------------------------
// fp16 scatter-aggregate: half-warp per edge, 128-bit REDs (proven R12).
// ---------------------------------------------------------------------------
#define EPW 8
__global__ void scatter16_kernel(const __half* __restrict__ feat,
                                 const int* __restrict__ ei,
                                 __half* __restrict__ agg) {
    int gw = (blockIdx.x * blockDim.x + threadIdx.x) >> 5;
    int lane = threadIdx.x & 31;
    int half = lane >> 4;
    int hl = lane & 15;
    int e0 = gw * EPW;
    if (e0 >= EE) return;

    uint4 v[EPW / 2];
    int d[EPW / 2];
#pragma unroll
    for (int t = 0; t < EPW / 2; t++) {
        int e = e0 + 2 * t + half;
        if (e < EE) {
            int s = __ldg(&ei[e]);
            d[t] = __ldg(&ei[EE + e]);
            v[t] = ((const uint4*)(feat + (size_t)s * DD))[hl];
        }
    }
#pragma unroll
    for (int t = 0; t < EPW / 2; t++) {
        int e = e0 + 2 * t + half;
        if (e < EE) {
            const __half* dp = agg + (size_t)d[t] * DD + hl * 8;
            asm volatile("red.global.add.noftz.v4.f16x2 [%0], {%1, %2, %3, %4};"
                         :: "l"(dp), "r"(v[t].x), "r"(v[t].y),
                            "r"(v[t].z), "r"(v[t].w)
                         : "memory");
        }
    }
}

// ---------------------------------------------------------------------------
// MMA GEMM: out = act( agg@Wrel + X@Wroot + bias ), m16n8k16 fp16 HMMA.
// 3 passes accumulate into fp32 D fragments:
//   (agg, Wrel_hi) (agg, Wrel_lo) (Xh, Wroot_hi)
// (x-side lo passes dropped: agg term dominates output magnitude ~3.5x, so
//  x-side rounding is attenuated; predicted rel_err ~5.2e-4 < 1e-3.)
// W tiles double-buffered. Optionally zeroes consumed A16 rows (next layer).
// Smem: 2 A-tiles + 2 W slots, each 34816 B = 139264 B.
// ---------------------------------------------------------------------------
#define GSM_A   0
#define GSM_XH  34816
#define GSM_W0  69632
#define GSM_W1  104448
#define GSMEM   139264

__device__ __forceinline__ uint32_t smem_u32(const void* p) {
    uint32_t a;
    asm("{ .reg .u64 t; cvta.to.shared.u64 t, %1; cvt.u32.u64 %0, t; }"
        : "=r"(a) : "l"(p));
    return a;
}

__global__ __launch_bounds__(512, 1)
void gemm_mma_kernel(const __half* __restrict__ A16,  // aggregated fp16 [N,128]
                     __half* __restrict__ aggz,       // same buffer, to zero (or null)
                     const __half* __restrict__ Xh,   // root fp16 [N,128]
                     const __half* __restrict__ wth_rel,
                     const __half* __restrict__ wtl_rel,
                     const __half* __restrict__ wth_root,
                     const float* __restrict__ bias,
                     float* __restrict__ out32,       // fp32 out (or null)
                     __half* __restrict__ outh,       // fp16 out (or null)
                     int relu) {
    extern __shared__ char sm[];
    uint32_t sbase = smem_u32(sm);
    int tid = threadIdx.x, wid = tid >> 5, lane = tid & 31;
    int row0 = blockIdx.x * 128;

    // Stage 2 A-tiles: global [N][128]h -> smem [128][PST]h (row pad 272 B)
    for (int w = tid; w < 128 * 16; w += 512) {
        int r = w >> 4, c = w & 15;
        int grow = row0 + r;
        uint4 va, vh;
        if (grow < NN) {
            va = ((const uint4*)(A16 + (size_t)grow * DD))[c];
            vh = ((const uint4*)(Xh + (size_t)grow * DD))[c];
        } else {
            va = make_uint4(0, 0, 0, 0);
            vh = va;
        }
        *(uint4*)(sm + GSM_A  + r * 272 + c * 16) = va;
        *(uint4*)(sm + GSM_XH + r * 272 + c * 16) = vh;
    }
    // Pre-stage pass-0 W (Wrel_hi) into slot 0
    for (int i = tid; i < 2176; i += 512)
        ((uint4*)(sm + GSM_W0))[i] = ((const uint4*)wth_rel)[i];
    __syncthreads();

    int rw = wid & 7;       // row-block
    int cw = wid >> 3;      // col-block

    float d[8][4];
#pragma unroll
    for (int i = 0; i < 8; i++)
#pragma unroll
        for (int j = 0; j < 4; j++) d[i][j] = 0.f;

    int a_row  = rw * 16 + ((lane >> 3) & 1) * 8 + (lane & 7);
    int a_koff = (lane >> 4) * 8;
    uint32_t a_off = (uint32_t)(a_row * 272 + a_koff * 2);
    int b_mat = lane >> 3;
    int b_line = cw * 64 + ((b_mat >> 1) & 1) * 8 + (lane & 7);
    int b_koff = (b_mat & 1) * 8;
    uint32_t b_rel = (uint32_t)(b_line * 272 + b_koff * 2);

    const uint32_t aoff[3] = {GSM_A, GSM_A, GSM_XH};
    const int wslot[3] = {0, 1, 0};
    const __half* wnext[3] = {wtl_rel, wth_root, nullptr};

#pragma unroll 1
    for (int p = 0; p < 3; p++) {
        // Stage next pass's W into the other slot (overlaps with MMAs below)
        if (wnext[p]) {
            uint32_t dstoff = (wslot[p + 1] == 0) ? GSM_W0 : GSM_W1;
            const uint4* src = (const uint4*)wnext[p];
            for (int i = tid; i < 2176; i += 512)
                ((uint4*)(sm + dstoff))[i] = src[i];
        }

        uint32_t abase = sbase + aoff[p] + a_off;
        uint32_t b_off = sbase + ((wslot[p] == 0) ? GSM_W0 : GSM_W1) + b_rel;
#pragma unroll
        for (int ks = 0; ks < 8; ks++) {
            uint32_t a0, a1, a2, a3;
            asm volatile(
                "ldmatrix.sync.aligned.m8n8.x4.shared.b16 {%0,%1,%2,%3}, [%4];"
                : "=r"(a0), "=r"(a1), "=r"(a2), "=r"(a3)
                : "r"(abase + ks * 32));
            uint32_t b[4][4];
#pragma unroll
            for (int bq = 0; bq < 4; bq++) {
                asm volatile(
                    "ldmatrix.sync.aligned.m8n8.x4.shared.b16 {%0,%1,%2,%3}, [%4];"
                    : "=r"(b[bq][0]), "=r"(b[bq][1]), "=r"(b[bq][2]), "=r"(b[bq][3])
                    : "r"(b_off + bq * (16 * 272) + ks * 32));
            }
#pragma unroll
            for (int nf = 0; nf < 8; nf++) {
                uint32_t b0 = b[nf >> 1][(nf & 1) * 2];
                uint32_t b1 = b[nf >> 1][(nf & 1) * 2 + 1];
                asm volatile(
                    "mma.sync.aligned.m16n8k16.row.col.f32.f16.f16.f32 "
                    "{%0,%1,%2,%3}, {%4,%5,%6,%7}, {%8,%9}, {%0,%1,%2,%3};"
                    : "+f"(d[nf][0]), "+f"(d[nf][1]), "+f"(d[nf][2]), "+f"(d[nf][3])
                    : "r"(a0), "r"(a1), "r"(a2), "r"(a3), "r"(b0), "r"(b1));
            }
        }
        __syncthreads();   // W(p+1) staged AND everyone done reading W(p)
    }

    // Zero the consumed aggregate rows for the next layer's scatter
    if (aggz) {
        uint4 z = make_uint4(0, 0, 0, 0);
        for (int w = tid; w < 128 * 16; w += 512) {
            int r = w >> 4, c = w & 15;
            int grow = row0 + r;
            if (grow < NN) ((uint4*)(aggz + (size_t)grow * DD))[c] = z;
        }
    }

    // Epilogue straight from fragments
    int er0 = row0 + rw * 16 + (lane >> 2);
#pragma unroll
    for (int nf = 0; nf < 8; nf++) {
        int c = cw * 64 + nf * 8 + 2 * (lane & 3);
        float bz0 = __ldg(&bias[c]);
        float bz1 = __ldg(&bias[c + 1]);
#pragma unroll
        for (int half = 0; half < 2; half++) {
            int grow = er0 + half * 8;
            if (grow < NN) {
                float v0 = d[nf][half * 2 + 0] + bz0;
                float v1 = d[nf][half * 2 + 1] + bz1;
                if (relu) { v0 = fmaxf(v0, 0.f); v1 = fmaxf(v1, 0.f); }
                if (out32)
                    *(float2*)(out32 + (size_t)grow * DD + c) = make_float2(v0, v1);
                if (outh) {
                    __half2 hh = __floats2half2_rn(v0, v1);
                    *(__half2*)(outh + (size_t)grow * DD + c) = hh;
                }
            }
        }
    }
}

// ---------------------------------------------------------------------------
// Launch
// ---------------------------------------------------------------------------
extern "C" void kernel_launch(void* const* d_in, const int* in_sizes, int n_in,
                              void* d_out, int out_size) {
    const float* x       = (const float*)d_in[0];
    const int*   ei      = (const int*)d_in[1];   // int32 (JAX x64 disabled)
    const float* W1_rel  = (const float*)d_in[2];
    const float* b1_rel  = (const float*)d_in[3];
    const float* W1_root = (const float*)d_in[4];
    const float* W2_rel  = (const float*)d_in[5];
    const float* b2_rel  = (const float*)d_in[6];
    const float* W2_root = (const float*)d_in[7];
    float*       out     = (float*)d_out;

    __half *agg16, *xh, *hh, *wth, *wtl;
    cudaGetSymbolAddress((void**)&agg16, g_agg16);
    cudaGetSymbolAddress((void**)&xh, g_xh);
    cudaGetSymbolAddress((void**)&hh, g_hh);
    cudaGetSymbolAddress((void**)&wth, g_wth);
    cudaGetSymbolAddress((void**)&wtl, g_wtl);

    cudaFuncSetAttribute(gemm_mma_kernel,
                         cudaFuncAttributeMaxDynamicSharedMemorySize,
                         (int)GSMEM);

    const int n4 = NN * DD / 4;
    const int n4h = NN * DD * 2 / 16;
    const int zgrid = (n4h + 255) / 256;
    const int nwarp = (EE + EPW - 1) / EPW;
    const int sgrid = (nwarp * 32 + 255) / 256;
    const int ggrid = (NN + 127) / 128;          // 391

    // Prep (once per launch)
    tohalf_kernel<<<(n4 + 255) / 256, 256>>>((const float4*)x, (uint2*)xh, n4);
    wprep_kernel<<<(4 * 16384 + 255) / 256, 256>>>(W1_rel, W1_root,
                                                   W2_rel, W2_root, wth, wtl);

    const int WM = 128 * PST;

    // Layer 1: A=agg(xh), X=xh; emits hh; zeroes agg16 for layer 2
    zero_kernel<<<zgrid, 256>>>((float4*)agg16, n4h);
    scatter16_kernel<<<sgrid, 256>>>(xh, ei, agg16);
    gemm_mma_kernel<<<ggrid, 512, GSMEM>>>(agg16, agg16, xh,
                                           wth + 0 * WM, wtl + 0 * WM,
                                           wth + 1 * WM,
                                           b1_rel, nullptr, hh, 1);

    // Layer 2: A=agg(hh), X=hh; emits fp32 out
    scatter16_kernel<<<sgrid, 256>>>(hh, ei, agg16);
    gemm_mma_kernel<<<ggrid, 512, GSMEM>>>(agg16, nullptr, hh,
                                           wth + 2 * WM, wtl + 2 * WM,
                                           wth + 3 * WM,
                                           b2_rel, out, nullptr, 0);
}

// round 14
// speedup vs baseline: 2.3062x; 1.1931x over previous
#include <cuda_runtime.h>
#include <cuda_fp16.h>
#include <cstdint>

// Problem constants
#define NN 50000
#define DD 128
#define EE 625000
#define PST 136          // padded row stride in halves (272 B) for ldmatrix

// Scratch (allocation-free rule: __device__ globals)
__device__ __half g_agg16[(size_t)NN * DD];
__device__ __half g_xh[(size_t)NN * DD];
__device__ __half g_hh[(size_t)NN * DD];
// Transposed fp16 weights, padded [128 n][PST k]:
// 0=W1_rel 1=W1_root 2=W2_rel 3=W2_root
__device__ __half g_wth[4 * 128 * PST];

// ---------------------------------------------------------------------------
// Zero kernel
// ---------------------------------------------------------------------------
__global__ void zero_kernel(float4* __restrict__ p, int n4) {
    int i = blockIdx.x * blockDim.x + threadIdx.x;
    if (i < n4) p[i] = make_float4(0.f, 0.f, 0.f, 0.f);
}

// ---------------------------------------------------------------------------
// fp32 -> fp16 convert (x -> xh)
// ---------------------------------------------------------------------------
__global__ void tohalf_kernel(const float4* __restrict__ src,
                              uint2* __restrict__ dst, int n4) {
    int i = blockIdx.x * blockDim.x + threadIdx.x;
    if (i < n4) {
        float4 v = src[i];
        __half2 a = __floats2half2_rn(v.x, v.y);
        __half2 b = __floats2half2_rn(v.z, v.w);
        dst[i] = make_uint2(*(unsigned*)&a, *(unsigned*)&b);
    }
}

// ---------------------------------------------------------------------------
// Weight prep: W[k][n] fp32 -> W^T fp16 padded [n][PST]
// ---------------------------------------------------------------------------
__global__ void wprep_kernel(const float* __restrict__ w0,
                             const float* __restrict__ w1,
                             const float* __restrict__ w2,
                             const float* __restrict__ w3,
                             __half* __restrict__ wth) {
    int g = blockIdx.x * blockDim.x + threadIdx.x;
    if (g >= 4 * 128 * 128) return;
    int m = g >> 14, e = g & 16383;
    int n = e >> 7, k = e & 127;
    const float* W = (m == 0) ? w0 : (m == 1) ? w1 : (m == 2) ? w2 : w3;
    wth[m * 128 * PST + n * PST + k] = __float2half_rn(W[k * 128 + n]);
}

// ---------------------------------------------------------------------------
// fp16 scatter-aggregate: half-warp per edge, 128-bit REDs (proven R12).
// ---------------------------------------------------------------------------
#define EPW 8
__global__ void scatter16_kernel(const __half* __restrict__ feat,
                                 const int* __restrict__ ei,
                                 __half* __restrict__ agg) {
    int gw = (blockIdx.x * blockDim.x + threadIdx.x) >> 5;
    int lane = threadIdx.x & 31;
    int half = lane >> 4;
    int hl = lane & 15;
    int e0 = gw * EPW;
    if (e0 >= EE) return;

    uint4 v[EPW / 2];
    int d[EPW / 2];
#pragma unroll
    for (int t = 0; t < EPW / 2; t++) {
        int e = e0 + 2 * t + half;
        if (e < EE) {
            int s = __ldg(&ei[e]);
            d[t] = __ldg(&ei[EE + e]);
            v[t] = ((const uint4*)(feat + (size_t)s * DD))[hl];
        }
    }
#pragma unroll
    for (int t = 0; t < EPW / 2; t++) {
        int e = e0 + 2 * t + half;
        if (e < EE) {
            const __half* dp = agg + (size_t)d[t] * DD + hl * 8;
            asm volatile("red.global.add.noftz.v4.f16x2 [%0], {%1, %2, %3, %4};"
                         :: "l"(dp), "r"(v[t].x), "r"(v[t].y),
                            "r"(v[t].z), "r"(v[t].w)
                         : "memory");
        }
    }
}

// ---------------------------------------------------------------------------
// MMA GEMM: out = act( agg@Wrel + X@Wroot + bias ), m16n8k16 fp16 HMMA.
// 2 passes, all-fp16-hi operands: (agg, Wrel) (Xh, Wroot).
// All four tiles staged up front; ONE sync; no inter-pass barriers.
// Smem: A + XH + W0 + W1, each 34816 B = 139264 B.
// ---------------------------------------------------------------------------
#define GSM_A   0
#define GSM_XH  34816
#define GSM_W0  69632
#define GSM_W1  104448
#define GSMEM   139264

__device__ __forceinline__ uint32_t smem_u32(const void* p) {
    uint32_t a;
    asm("{ .reg .u64 t; cvta.to.shared.u64 t, %1; cvt.u32.u64 %0, t; }"
        : "=r"(a) : "l"(p));
    return a;
}

__global__ __launch_bounds__(512, 1)
void gemm_mma_kernel(const __half* __restrict__ A16,  // aggregated fp16 [N,128]
                     __half* __restrict__ aggz,       // same buffer, to zero (or null)
                     const __half* __restrict__ Xh,   // root fp16 [N,128]
                     const __half* __restrict__ wth_rel,
                     const __half* __restrict__ wth_root,
                     const float* __restrict__ bias,
                     float* __restrict__ out32,       // fp32 out (or null)
                     __half* __restrict__ outh,       // fp16 out (or null)
                     int relu) {
    extern __shared__ char sm[];
    uint32_t sbase = smem_u32(sm);
    int tid = threadIdx.x, wid = tid >> 5, lane = tid & 31;
    int row0 = blockIdx.x * 128;

    // Stage 2 A-tiles: global [N][128]h -> smem [128][PST]h (row pad 272 B)
    for (int w = tid; w < 128 * 16; w += 512) {
        int r = w >> 4, c = w & 15;
        int grow = row0 + r;
        uint4 va, vh;
        if (grow < NN) {
            va = ((const uint4*)(A16 + (size_t)grow * DD))[c];
            vh = ((const uint4*)(Xh + (size_t)grow * DD))[c];
        } else {
            va = make_uint4(0, 0, 0, 0);
            vh = va;
        }
        *(uint4*)(sm + GSM_A  + r * 272 + c * 16) = va;
        *(uint4*)(sm + GSM_XH + r * 272 + c * 16) = vh;
    }
    // Stage both W tiles up front
    for (int i = tid; i < 2176; i += 512) {
        ((uint4*)(sm + GSM_W0))[i] = ((const uint4*)wth_rel)[i];
        ((uint4*)(sm + GSM_W1))[i] = ((const uint4*)wth_root)[i];
    }
    __syncthreads();

    int rw = wid & 7;       // row-block
    int cw = wid >> 3;      // col-block

    float d[8][4];
#pragma unroll
    for (int i = 0; i < 8; i++)
#pragma unroll
        for (int j = 0; j < 4; j++) d[i][j] = 0.f;

    int a_row  = rw * 16 + ((lane >> 3) & 1) * 8 + (lane & 7);
    int a_koff = (lane >> 4) * 8;
    uint32_t a_off = (uint32_t)(a_row * 272 + a_koff * 2);
    int b_mat = lane >> 3;
    int b_line = cw * 64 + ((b_mat >> 1) & 1) * 8 + (lane & 7);
    int b_koff = (b_mat & 1) * 8;
    uint32_t b_rel = (uint32_t)(b_line * 272 + b_koff * 2);

    const uint32_t aoff[2] = {GSM_A, GSM_XH};
    const uint32_t woff[2] = {GSM_W0, GSM_W1};

#pragma unroll
    for (int p = 0; p < 2; p++) {
        uint32_t abase = sbase + aoff[p] + a_off;
        uint32_t b_off = sbase + woff[p] + b_rel;
#pragma unroll
        for (int ks = 0; ks < 8; ks++) {
            uint32_t a0, a1, a2, a3;
            asm volatile(
                "ldmatrix.sync.aligned.m8n8.x4.shared.b16 {%0,%1,%2,%3}, [%4];"
                : "=r"(a0), "=r"(a1), "=r"(a2), "=r"(a3)
                : "r"(abase + ks * 32));
            uint32_t b[4][4];
#pragma unroll
            for (int bq = 0; bq < 4; bq++) {
                asm volatile(
                    "ldmatrix.sync.aligned.m8n8.x4.shared.b16 {%0,%1,%2,%3}, [%4];"
                    : "=r"(b[bq][0]), "=r"(b[bq][1]), "=r"(b[bq][2]), "=r"(b[bq][3])
                    : "r"(b_off + bq * (16 * 272) + ks * 32));
            }
#pragma unroll
            for (int nf = 0; nf < 8; nf++) {
                uint32_t b0 = b[nf >> 1][(nf & 1) * 2];
                uint32_t b1 = b[nf >> 1][(nf & 1) * 2 + 1];
                asm volatile(
                    "mma.sync.aligned.m16n8k16.row.col.f32.f16.f16.f32 "
                    "{%0,%1,%2,%3}, {%4,%5,%6,%7}, {%8,%9}, {%0,%1,%2,%3};"
                    : "+f"(d[nf][0]), "+f"(d[nf][1]), "+f"(d[nf][2]), "+f"(d[nf][3])
                    : "r"(a0), "r"(a1), "r"(a2), "r"(a3), "r"(b0), "r"(b1));
            }
        }
    }

    // Zero the consumed aggregate rows for the next layer's scatter
    if (aggz) {
        uint4 z = make_uint4(0, 0, 0, 0);
        for (int w = tid; w < 128 * 16; w += 512) {
            int r = w >> 4, c = w & 15;
            int grow = row0 + r;
            if (grow < NN) ((uint4*)(aggz + (size_t)grow * DD))[c] = z;
        }
    }

    // Epilogue straight from fragments
    int er0 = row0 + rw * 16 + (lane >> 2);
#pragma unroll
    for (int nf = 0; nf < 8; nf++) {
        int c = cw * 64 + nf * 8 + 2 * (lane & 3);
        float bz0 = __ldg(&bias[c]);
        float bz1 = __ldg(&bias[c + 1]);
#pragma unroll
        for (int half = 0; half < 2; half++) {
            int grow = er0 + half * 8;
            if (grow < NN) {
                float v0 = d[nf][half * 2 + 0] + bz0;
                float v1 = d[nf][half * 2 + 1] + bz1;
                if (relu) { v0 = fmaxf(v0, 0.f); v1 = fmaxf(v1, 0.f); }
                if (out32)
                    *(float2*)(out32 + (size_t)grow * DD + c) = make_float2(v0, v1);
                if (outh) {
                    __half2 hh = __floats2half2_rn(v0, v1);
                    *(__half2*)(outh + (size_t)grow * DD + c) = hh;
                }
            }
        }
    }
}

// ---------------------------------------------------------------------------
// Launch
// ---------------------------------------------------------------------------
extern "C" void kernel_launch(void* const* d_in, const int* in_sizes, int n_in,
                              void* d_out, int out_size) {
    const float* x       = (const float*)d_in[0];
    const int*   ei      = (const int*)d_in[1];   // int32 (JAX x64 disabled)
    const float* W1_rel  = (const float*)d_in[2];
    const float* b1_rel  = (const float*)d_in[3];
    const float* W1_root = (const float*)d_in[4];
    const float* W2_rel  = (const float*)d_in[5];
    const float* b2_rel  = (const float*)d_in[6];
    const float* W2_root = (const float*)d_in[7];
    float*       out     = (float*)d_out;

    __half *agg16, *xh, *hh, *wth;
    cudaGetSymbolAddress((void**)&agg16, g_agg16);
    cudaGetSymbolAddress((void**)&xh, g_xh);
    cudaGetSymbolAddress((void**)&hh, g_hh);
    cudaGetSymbolAddress((void**)&wth, g_wth);

    cudaFuncSetAttribute(gemm_mma_kernel,
                         cudaFuncAttributeMaxDynamicSharedMemorySize,
                         (int)GSMEM);

    const int n4 = NN * DD / 4;
    const int n4h = NN * DD * 2 / 16;
    const int zgrid = (n4h + 255) / 256;
    const int nwarp = (EE + EPW - 1) / EPW;
    const int sgrid = (nwarp * 32 + 255) / 256;
    const int ggrid = (NN + 127) / 128;          // 391

    // Prep (once per launch)
    tohalf_kernel<<<(n4 + 255) / 256, 256>>>((const float4*)x, (uint2*)xh, n4);
    wprep_kernel<<<(4 * 16384 + 255) / 256, 256>>>(W1_rel, W1_root,
                                                   W2_rel, W2_root, wth);

    const int WM = 128 * PST;

    // Layer 1: A=agg(xh), X=xh; emits hh; zeroes agg16 for layer 2
    zero_kernel<<<zgrid, 256>>>((float4*)agg16, n4h);
    scatter16_kernel<<<sgrid, 256>>>(xh, ei, agg16);
    gemm_mma_kernel<<<ggrid, 512, GSMEM>>>(agg16, agg16, xh,
                                           wth + 0 * WM, wth + 1 * WM,
                                           b1_rel, nullptr, hh, 1);

    // Layer 2: A=agg(hh), X=hh; emits fp32 out
    scatter16_kernel<<<sgrid, 256>>>(hh, ei, agg16);
    gemm_mma_kernel<<<ggrid, 512, GSMEM>>>(agg16, nullptr, hh,
                                           wth + 2 * WM, wth + 3 * WM,
                                           b2_rel, out, nullptr, 0);
}

// round 15
// speedup vs baseline: 2.3200x; 1.0060x over previous
#include <cuda_runtime.h>
#include <cuda_fp16.h>
#include <cstdint>

// Problem constants
#define NN 50000
#define DD 128
#define EE 625000
#define PST 136          // padded row stride in halves (272 B) for ldmatrix

// Scratch (allocation-free rule: __device__ globals)
__device__ __half g_agg16[(size_t)NN * DD];
__device__ __half g_xh[(size_t)NN * DD];
__device__ __half g_hh[(size_t)NN * DD];
// Transposed fp16 weights, padded [128 n][PST k]:
// 0=W1_rel 1=W1_root 2=W2_rel 3=W2_root
__device__ __half g_wth[4 * 128 * PST];

// ---------------------------------------------------------------------------
// Fused prep: zero agg16 | x->xh fp16 convert | weight transpose->fp16.
// Flat index over three ranges (saves 2 kernel launches).
// ---------------------------------------------------------------------------
#define PREP_Z   (NN * DD / 8)            // uint4 count of agg16 (800000)
#define PREP_C   (NN * DD / 4)            // float4 count of x (1600000)
#define PREP_W   (4 * 128 * 128)          // weight elements (65536)
#define PREP_TOT (PREP_Z + PREP_C + PREP_W)

__global__ void prep_kernel(const float4* __restrict__ x,
                            const float* __restrict__ w0,
                            const float* __restrict__ w1,
                            const float* __restrict__ w2,
                            const float* __restrict__ w3,
                            uint4* __restrict__ aggz,
                            uint2* __restrict__ xh,
                            __half* __restrict__ wth) {
    int i = blockIdx.x * blockDim.x + threadIdx.x;
    if (i < PREP_Z) {
        aggz[i] = make_uint4(0, 0, 0, 0);
    } else if (i < PREP_Z + PREP_C) {
        int j = i - PREP_Z;
        float4 v = x[j];
        __half2 a = __floats2half2_rn(v.x, v.y);
        __half2 b = __floats2half2_rn(v.z, v.w);
        xh[j] = make_uint2(*(unsigned*)&a, *(unsigned*)&b);
    } else if (i < PREP_TOT) {
        int g = i - PREP_Z - PREP_C;
        int m = g >> 14, e = g & 16383;
        int n = e >> 7, k = e & 127;
        const float* W = (m == 0) ? w0 : (m == 1) ? w1 : (m == 2) ? w2 : w3;
        wth[m * 128 * PST + n * PST + k] = __float2half_rn(W[k * 128 + n]);
    }
}

// ---------------------------------------------------------------------------
// fp16 scatter-aggregate: half-warp per edge, 128-bit REDs (proven R12).
// ---------------------------------------------------------------------------
#define EPW 8
__global__ void scatter16_kernel(const __half* __restrict__ feat,
                                 const int* __restrict__ ei,
                                 __half* __restrict__ agg) {
    int gw = (blockIdx.x * blockDim.x + threadIdx.x) >> 5;
    int lane = threadIdx.x & 31;
    int half = lane >> 4;
    int hl = lane & 15;
    int e0 = gw * EPW;
    if (e0 >= EE) return;

    uint4 v[EPW / 2];
    int d[EPW / 2];
#pragma unroll
    for (int t = 0; t < EPW / 2; t++) {
        int e = e0 + 2 * t + half;
        if (e < EE) {
            int s = __ldg(&ei[e]);
            d[t] = __ldg(&ei[EE + e]);
            v[t] = ((const uint4*)(feat + (size_t)s * DD))[hl];
        }
    }
#pragma unroll
    for (int t = 0; t < EPW / 2; t++) {
        int e = e0 + 2 * t + half;
        if (e < EE) {
            const __half* dp = agg + (size_t)d[t] * DD + hl * 8;
            asm volatile("red.global.add.noftz.v4.f16x2 [%0], {%1, %2, %3, %4};"
                         :: "l"(dp), "r"(v[t].x), "r"(v[t].y),
                            "r"(v[t].z), "r"(v[t].w)
                         : "memory");
        }
    }
}

// ---------------------------------------------------------------------------
// MMA GEMM: out = act( agg@Wrel + X@Wroot + bias ), m16n8k16 fp16 HMMA.
// 2 passes, all-fp16 operands: (agg, Wrel) (Xh, Wroot).
// 64-row tiles, 256 threads, 2 CTAs/SM (halves wave-quantization loss,
// doubles per-SM warps for latency hiding).
// 8 warps: rw = wid&3 (4 row-blocks x 16), cw = wid>>2 (2 col-blocks x 64).
// Smem per CTA: A(17408) + X(17408) + W0(34816) + W1(34816) = 104448 B.
// ---------------------------------------------------------------------------
#define GSM_A   0
#define GSM_XH  17408
#define GSM_W0  34816
#define GSM_W1  69632
#define GSMEM   104448

__device__ __forceinline__ uint32_t smem_u32(const void* p) {
    uint32_t a;
    asm("{ .reg .u64 t; cvta.to.shared.u64 t, %1; cvt.u32.u64 %0, t; }"
        : "=r"(a) : "l"(p));
    return a;
}

__global__ __launch_bounds__(256, 2)
void gemm_mma_kernel(const __half* __restrict__ A16,  // aggregated fp16 [N,128]
                     __half* __restrict__ aggz,       // same buffer, to zero (or null)
                     const __half* __restrict__ Xh,   // root fp16 [N,128]
                     const __half* __restrict__ wth_rel,
                     const __half* __restrict__ wth_root,
                     const float* __restrict__ bias,
                     float* __restrict__ out32,       // fp32 out (or null)
                     __half* __restrict__ outh,       // fp16 out (or null)
                     int relu) {
    extern __shared__ char sm[];
    uint32_t sbase = smem_u32(sm);
    int tid = threadIdx.x, wid = tid >> 5, lane = tid & 31;
    int row0 = blockIdx.x * 64;

    // Stage 2 A-tiles: global [N][128]h -> smem [64][PST]h (row pad 272 B)
    for (int w = tid; w < 64 * 16; w += 256) {
        int r = w >> 4, c = w & 15;
        int grow = row0 + r;
        uint4 va, vh;
        if (grow < NN) {
            va = ((const uint4*)(A16 + (size_t)grow * DD))[c];
            vh = ((const uint4*)(Xh + (size_t)grow * DD))[c];
        } else {
            va = make_uint4(0, 0, 0, 0);
            vh = va;
        }
        *(uint4*)(sm + GSM_A  + r * 272 + c * 16) = va;
        *(uint4*)(sm + GSM_XH + r * 272 + c * 16) = vh;
    }
    // Stage both W tiles (128 n rows x PST halves each)
    for (int i = tid; i < 2176; i += 256) {
        ((uint4*)(sm + GSM_W0))[i] = ((const uint4*)wth_rel)[i];
        ((uint4*)(sm + GSM_W1))[i] = ((const uint4*)wth_root)[i];
    }
    __syncthreads();

    int rw = wid & 3;       // row-block (4 x 16 rows = 64)
    int cw = wid >> 2;      // col-block (2 x 64 cols = 128)

    float d[8][4];
#pragma unroll
    for (int i = 0; i < 8; i++)
#pragma unroll
        for (int j = 0; j < 4; j++) d[i][j] = 0.f;

    int a_row  = rw * 16 + ((lane >> 3) & 1) * 8 + (lane & 7);
    int a_koff = (lane >> 4) * 8;
    uint32_t a_off = (uint32_t)(a_row * 272 + a_koff * 2);
    int b_mat = lane >> 3;
    int b_line = cw * 64 + ((b_mat >> 1) & 1) * 8 + (lane & 7);
    int b_koff = (b_mat & 1) * 8;
    uint32_t b_rel = (uint32_t)(b_line * 272 + b_koff * 2);

    const uint32_t aoff[2] = {GSM_A, GSM_XH};
    const uint32_t woff[2] = {GSM_W0, GSM_W1};

#pragma unroll
    for (int p = 0; p < 2; p++) {
        uint32_t abase = sbase + aoff[p] + a_off;
        uint32_t b_off = sbase + woff[p] + b_rel;
#pragma unroll
        for (int ks = 0; ks < 8; ks++) {
            uint32_t a0, a1, a2, a3;
            asm volatile(
                "ldmatrix.sync.aligned.m8n8.x4.shared.b16 {%0,%1,%2,%3}, [%4];"
                : "=r"(a0), "=r"(a1), "=r"(a2), "=r"(a3)
                : "r"(abase + ks * 32));
            uint32_t b[4][4];
#pragma unroll
            for (int bq = 0; bq < 4; bq++) {
                asm volatile(
                    "ldmatrix.sync.aligned.m8n8.x4.shared.b16 {%0,%1,%2,%3}, [%4];"
                    : "=r"(b[bq][0]), "=r"(b[bq][1]), "=r"(b[bq][2]), "=r"(b[bq][3])
                    : "r"(b_off + bq * (16 * 272) + ks * 32));
            }
#pragma unroll
            for (int nf = 0; nf < 8; nf++) {
                uint32_t b0 = b[nf >> 1][(nf & 1) * 2];
                uint32_t b1 = b[nf >> 1][(nf & 1) * 2 + 1];
                asm volatile(
                    "mma.sync.aligned.m16n8k16.row.col.f32.f16.f16.f32 "
                    "{%0,%1,%2,%3}, {%4,%5,%6,%7}, {%8,%9}, {%0,%1,%2,%3};"
                    : "+f"(d[nf][0]), "+f"(d[nf][1]), "+f"(d[nf][2]), "+f"(d[nf][3])
                    : "r"(a0), "r"(a1), "r"(a2), "r"(a3), "r"(b0), "r"(b1));
            }
        }
    }

    // Zero the consumed aggregate rows for the next layer's scatter
    if (aggz) {
        uint4 z = make_uint4(0, 0, 0, 0);
        for (int w = tid; w < 64 * 16; w += 256) {
            int r = w >> 4, c = w & 15;
            int grow = row0 + r;
            if (grow < NN) ((uint4*)(aggz + (size_t)grow * DD))[c] = z;
        }
    }

    // Epilogue straight from fragments
    int er0 = row0 + rw * 16 + (lane >> 2);
#pragma unroll
    for (int nf = 0; nf < 8; nf++) {
        int c = cw * 64 + nf * 8 + 2 * (lane & 3);
        float bz0 = __ldg(&bias[c]);
        float bz1 = __ldg(&bias[c + 1]);
#pragma unroll
        for (int half = 0; half < 2; half++) {
            int grow = er0 + half * 8;
            if (grow < NN) {
                float v0 = d[nf][half * 2 + 0] + bz0;
                float v1 = d[nf][half * 2 + 1] + bz1;
                if (relu) { v0 = fmaxf(v0, 0.f); v1 = fmaxf(v1, 0.f); }
                if (out32)
                    *(float2*)(out32 + (size_t)grow * DD + c) = make_float2(v0, v1);
                if (outh) {
                    __half2 hh = __floats2half2_rn(v0, v1);
                    *(__half2*)(outh + (size_t)grow * DD + c) = hh;
                }
            }
        }
    }
}

// ---------------------------------------------------------------------------
// Launch
// ---------------------------------------------------------------------------
extern "C" void kernel_launch(void* const* d_in, const int* in_sizes, int n_in,
                              void* d_out, int out_size) {
    const float* x       = (const float*)d_in[0];
    const int*   ei      = (const int*)d_in[1];   // int32 (JAX x64 disabled)
    const float* W1_rel  = (const float*)d_in[2];
    const float* b1_rel  = (const float*)d_in[3];
    const float* W1_root = (const float*)d_in[4];
    const float* W2_rel  = (const float*)d_in[5];
    const float* b2_rel  = (const float*)d_in[6];
    const float* W2_root = (const float*)d_in[7];
    float*       out     = (float*)d_out;

    __half *agg16, *xh, *hh, *wth;
    cudaGetSymbolAddress((void**)&agg16, g_agg16);
    cudaGetSymbolAddress((void**)&xh, g_xh);
    cudaGetSymbolAddress((void**)&hh, g_hh);
    cudaGetSymbolAddress((void**)&wth, g_wth);

    cudaFuncSetAttribute(gemm_mma_kernel,
                         cudaFuncAttributeMaxDynamicSharedMemorySize,
                         (int)GSMEM);

    const int pgrid = (PREP_TOT + 255) / 256;
    const int nwarp = (EE + EPW - 1) / EPW;
    const int sgrid = (nwarp * 32 + 255) / 256;
    const int ggrid = (NN + 63) / 64;            // 782

    const int WM = 128 * PST;

    // Fused prep: zero agg16 + x->xh + weight transpose (once per launch)
    prep_kernel<<<pgrid, 256>>>((const float4*)x, W1_rel, W1_root,
                                W2_rel, W2_root,
                                (uint4*)agg16, (uint2*)xh, wth);

    // Layer 1: A=agg(xh), X=xh; emits hh; zeroes agg16 for layer 2
    scatter16_kernel<<<sgrid, 256>>>(xh, ei, agg16);
    gemm_mma_kernel<<<ggrid, 256, GSMEM>>>(agg16, agg16, xh,
                                           wth + 0 * WM, wth + 1 * WM,
                                           b1_rel, nullptr, hh, 1);

    // Layer 2: A=agg(hh), X=hh; emits fp32 out
    scatter16_kernel<<<sgrid, 256>>>(hh, ei, agg16);
    gemm_mma_kernel<<<ggrid, 256, GSMEM>>>(agg16, nullptr, hh,
                                           wth + 2 * WM, wth + 3 * WM,
                                           b2_rel, out, nullptr, 0);
}